// round 17
// baseline (speedup 1.0000x reference)
#include <cuda_runtime.h>
#include <cstdint>

// C4TransformerVM: exact 4-byte ripple-carry add over one-hot byte encodings
// -> decode (argmax), uint32 add (final carry discarded), re-encode one-hot.
// Irreducible traffic: 256 MB read + 128 MB write.
//
// Converged base (R11/R13, 54.4us @ 6572 GB/s): fused, v8.f32 256-bit ld/st,
// zero-store overlap + owner-lane patch, default cache policy.
// R17 experiment: 2 tiles per warp with ALL 16 v8 loads issued up front
// (unlike failed R7 where tile k+1 loads trailed tile k's REDUX). Doubles
// per-warp MLP, halves REDUX dead-window fraction. launch_bounds(128,3)
// gives ~170 regs for the ~150 needed.

__device__ __forceinline__ void ldg256(const float* p, float4& lo, float4& hi) {
    asm volatile(
        "ld.global.nc.v8.f32 {%0,%1,%2,%3,%4,%5,%6,%7}, [%8];"
        : "=f"(lo.x), "=f"(lo.y), "=f"(lo.z), "=f"(lo.w),
          "=f"(hi.x), "=f"(hi.y), "=f"(hi.z), "=f"(hi.w)
        : "l"(p));
}

__device__ __forceinline__ void stg256_zero(float* p) {
    asm volatile(
        "st.global.v8.f32 [%0], {%1,%1,%1,%1,%1,%1,%1,%1};"
        :: "l"(p), "f"(0.0f) : "memory");
}

__device__ __forceinline__ uint32_t scan8_mask(float4 v0, float4 v1, int base, int sh) {
    uint32_t idx = 0;
    if (v0.x > 0.5f) idx = (uint32_t)(base + 0);
    if (v0.y > 0.5f) idx = (uint32_t)(base + 1);
    if (v0.z > 0.5f) idx = (uint32_t)(base + 2);
    if (v0.w > 0.5f) idx = (uint32_t)(base + 3);
    if (v1.x > 0.5f) idx = (uint32_t)(base + 4);
    if (v1.y > 0.5f) idx = (uint32_t)(base + 5);
    if (v1.z > 0.5f) idx = (uint32_t)(base + 6);
    if (v1.w > 0.5f) idx = (uint32_t)(base + 7);
    return idx << sh;
}

__global__ __launch_bounds__(128, 3) void neural_alu_add_kernel(
    const float* __restrict__ a,
    const float* __restrict__ b,
    float* __restrict__ out,
    int N)
{
    const int warp_id = (blockIdx.x * blockDim.x + threadIdx.x) >> 5;
    const int lane = threadIdx.x & 31;
    const int half = N >> 1;
    if (warp_id >= half) return;
    const size_t n0 = (size_t)warp_id * 2;   // this warp owns n0 and n0+1
    const int base = lane * 8;

    // ---- Phase 1: issue ALL 16 v8 loads (both tiles) before consumption.
    float4 va0[8], vb0[8], va1[8], vb1[8];
#pragma unroll
    for (int i = 0; i < 4; i++) {
        const float* ra = a + ((size_t)i * N + n0) * 256 + base;
        const float* rb = b + ((size_t)i * N + n0) * 256 + base;
        ldg256(ra,        va0[2 * i], va0[2 * i + 1]);
        ldg256(ra + 256,  va1[2 * i], va1[2 * i + 1]);
        ldg256(rb,        vb0[2 * i], vb0[2 * i + 1]);
        ldg256(rb + 256,  vb1[2 * i], vb1[2 * i + 1]);
    }

    // ---- Phase 2: zero all 8 output rows (independent of in-flight loads).
#pragma unroll
    for (int i = 0; i < 4; i++) {
        float* ro = out + ((size_t)i * N + n0) * 256 + base;
        stg256_zero(ro);
        stg256_zero(ro + 256);
    }

    // ---- Phase 3: decode both tiles.
    uint32_t Ap0 = 0, Bp0 = 0, Ap1 = 0, Bp1 = 0;
#pragma unroll
    for (int i = 0; i < 4; i++) {
        Ap0 |= scan8_mask(va0[2 * i], va0[2 * i + 1], base, 8 * i);
        Bp0 |= scan8_mask(vb0[2 * i], vb0[2 * i + 1], base, 8 * i);
        Ap1 |= scan8_mask(va1[2 * i], va1[2 * i + 1], base, 8 * i);
        Bp1 |= scan8_mask(vb1[2 * i], vb1[2 * i + 1], base, 8 * i);
    }
    const uint32_t S0 = __reduce_or_sync(0xffffffffu, Ap0) +
                        __reduce_or_sync(0xffffffffu, Bp0);
    const uint32_t S1 = __reduce_or_sync(0xffffffffu, Ap1) +
                        __reduce_or_sync(0xffffffffu, Bp1);

    // ---- Phase 4: owner-lane patches (program order after the zero store).
#pragma unroll
    for (int i = 0; i < 4; i++) {
        const int r0 = (int)((S0 >> (8 * i)) & 255u);
        const int r1 = (int)((S1 >> (8 * i)) & 255u);
        float* ro = out + ((size_t)i * N + n0) * 256;
        if ((r0 >> 3) == lane) ro[r0] = 1.0f;
        if ((r1 >> 3) == lane) ro[256 + r1] = 1.0f;
    }
}

extern "C" void kernel_launch(void* const* d_in, const int* in_sizes, int n_in,
                              void* d_out, int out_size) {
    const float* a = (const float*)d_in[0];   // [4, N, 256] one-hot
    const float* b = (const float*)d_in[1];   // [4, N, 256] one-hot
    float* out = (float*)d_out;               // [4, N, 256]
    const int N = in_sizes[0] / (4 * 256);

    const int threads = 128;                  // 4 warps/block, 2 n per warp
    const int warps_needed = N / 2;
    const int blocks = (warps_needed * 32 + threads - 1) / threads;
    neural_alu_add_kernel<<<blocks, threads>>>(a, b, out, N);
}